// round 1
// baseline (speedup 1.0000x reference)
#include <cuda_runtime.h>
#include <cuda_bf16.h>
#include <math.h>

// ---------------------------------------------------------------------------
// TransformerBlock: B=4, L=2048 (T=8192 tokens), HIDDEN=1024, HEADS=16, HEAD=64,
// EXPAND=4096, post-norm, exact GELU, fp32.
//
// Pipeline:
//   1. qkv  = x @ Wqkv + bqkv                      (gemm)
//   2. attn = flash_attention(qkv)                 (flash kernel, no LxL scratch)
//   3. tmp  = attn @ Wproj + bproj                 (gemm)
//   4. h    = LN(x + tmp; g1, be1)                 (add_layernorm)
//   5. ff   = gelu(h @ W1 + b1)                    (gemm + gelu epilogue)
//   6. tmp  = ff @ W2 + b2                         (gemm)
//   7. out  = LN(h + tmp; g2, be2)                 (add_layernorm)
// ---------------------------------------------------------------------------

#define TOKENS 8192
#define HID    1024
#define NHEADS 16
#define DHEAD  64
#define EXP    4096
#define SEQ    2048
#define BATCH  4

// Scratch (static device globals — no allocation in kernel_launch)
__device__ float g_qkv[(size_t)TOKENS * 3 * HID];   // 96 MB
__device__ float g_attn[(size_t)TOKENS * HID];      // 32 MB
__device__ float g_h[(size_t)TOKENS * HID];         // 32 MB
__device__ float g_ff[(size_t)TOKENS * EXP];        // 128 MB
__device__ float g_tmp[(size_t)TOKENS * HID];       // 32 MB

// ---------------------------------------------------------------------------
// Tiled SGEMM: C[M,N] = A[M,K] @ B[K,N] + bias[N], optional exact-GELU epilogue.
// BM=BN=64, BK=16, 256 threads, 4x4 register tile per thread.
// All problem dims here are exact multiples of the tile sizes.
// ---------------------------------------------------------------------------
#define BM 64
#define BN 64
#define BK 16

__global__ __launch_bounds__(256) void gemm_bias_act(
    const float* __restrict__ A, const float* __restrict__ Bm,
    const float* __restrict__ bias, float* __restrict__ C,
    int M, int N, int K, int act)
{
    __shared__ float As[BK][BM + 4];
    __shared__ float Bs[BK][BN + 4];

    const int tid = threadIdx.x;
    const int tx = tid & 15;        // 0..15 -> 4 output cols each
    const int ty = tid >> 4;        // 0..15 -> 4 output rows each
    const int n0 = blockIdx.x * BN;
    const int m0 = blockIdx.y * BM;

    float acc[4][4];
#pragma unroll
    for (int i = 0; i < 4; i++)
#pragma unroll
        for (int j = 0; j < 4; j++) acc[i][j] = 0.0f;

    for (int k0 = 0; k0 < K; k0 += BK) {
        // Load A tile [BM x BK], store transposed As[k][m]
#pragma unroll
        for (int i = 0; i < 4; i++) {
            int e = tid + i * 256;          // 0..1023
            int r = e >> 4;                 // m-row 0..63
            int c = e & 15;                 // k-col 0..15
            As[c][r] = A[(size_t)(m0 + r) * K + (k0 + c)];
        }
        // Load B tile [BK x BN]
#pragma unroll
        for (int i = 0; i < 4; i++) {
            int e = tid + i * 256;
            int r = e >> 6;                 // k-row 0..15
            int c = e & 63;                 // n-col 0..63
            Bs[r][c] = Bm[(size_t)(k0 + r) * N + (n0 + c)];
        }
        __syncthreads();

#pragma unroll
        for (int k = 0; k < BK; k++) {
            float4 a4 = *(const float4*)&As[k][ty * 4];
            float4 b4 = *(const float4*)&Bs[k][tx * 4];
            float av[4] = {a4.x, a4.y, a4.z, a4.w};
            float bv[4] = {b4.x, b4.y, b4.z, b4.w};
#pragma unroll
            for (int i = 0; i < 4; i++)
#pragma unroll
                for (int j = 0; j < 4; j++)
                    acc[i][j] = fmaf(av[i], bv[j], acc[i][j]);
        }
        __syncthreads();
    }

    // Epilogue
#pragma unroll
    for (int i = 0; i < 4; i++) {
        int m = m0 + ty * 4 + i;
        float4 o;
        float* po = &o.x;
#pragma unroll
        for (int j = 0; j < 4; j++) {
            int n = n0 + tx * 4 + j;
            float v = acc[i][j] + bias[n];
            if (act == 1) {
                // exact GELU: 0.5*x*(1+erf(x/sqrt(2)))
                v = 0.5f * v * (1.0f + erff(v * 0.70710678118654752f));
            }
            po[j] = v;
        }
        *(float4*)&C[(size_t)m * N + (n0 + tx * 4)] = o;
    }
}

// ---------------------------------------------------------------------------
// Flash attention (fp32, online softmax). qkv layout: [tok, 3*HID] where
// q at col h*64+d, k at 1024+h*64+d, v at 2048+h*64+d.
// One thread per query row; K/V tiles of 16 keys staged in smem.
// grid = (SEQ/128, BATCH*NHEADS), block = 128.
// ---------------------------------------------------------------------------
#define TK 16

__global__ __launch_bounds__(128) void flash_attn(
    const float* __restrict__ qkv, float* __restrict__ out)
{
    const int bh = blockIdx.y;
    const int b = bh >> 4;          // /16
    const int h = bh & 15;
    const int l = blockIdx.x * 128 + threadIdx.x;
    const int tok = b * SEQ + l;

    __shared__ float ks[TK][DHEAD];
    __shared__ float vs[TK][DHEAD];

    // Load q, pre-scaled by 1/sqrt(64)
    float q[DHEAD];
    const float* qrow = qkv + (size_t)tok * 3072 + h * DHEAD;
#pragma unroll
    for (int d = 0; d < DHEAD; d += 4) {
        float4 t = *(const float4*)&qrow[d];
        q[d + 0] = t.x * 0.125f;
        q[d + 1] = t.y * 0.125f;
        q[d + 2] = t.z * 0.125f;
        q[d + 3] = t.w * 0.125f;
    }

    float acc[DHEAD];
#pragma unroll
    for (int d = 0; d < DHEAD; d++) acc[d] = 0.0f;
    float mval = -INFINITY;
    float lsum = 0.0f;

    const size_t kbase = (size_t)b * SEQ * 3072 + 1024 + h * DHEAD;
    const size_t vbase = kbase + 1024;

    for (int j0 = 0; j0 < SEQ; j0 += TK) {
        __syncthreads();
        // cooperative load of TK keys + values: TK*64/4 = 256 float4 each
        for (int i = threadIdx.x; i < TK * (DHEAD / 4); i += 128) {
            int j = i >> 4;           // key within tile
            int d4 = i & 15;          // float4 within head dim
            size_t roff = (size_t)(j0 + j) * 3072 + d4 * 4;
            *(float4*)&ks[j][d4 * 4] = *(const float4*)&qkv[kbase + roff];
            *(float4*)&vs[j][d4 * 4] = *(const float4*)&qkv[vbase + roff];
        }
        __syncthreads();

        float sc[TK];
        float tmax = mval;
#pragma unroll
        for (int j = 0; j < TK; j++) {
            float s = 0.0f;
#pragma unroll
            for (int d = 0; d < DHEAD; d++)
                s = fmaf(q[d], ks[j][d], s);
            sc[j] = s;
            tmax = fmaxf(tmax, s);
        }
        float corr = __expf(mval - tmax);   // exp(-inf - finite) = 0 on first tile
        mval = tmax;
        lsum *= corr;
#pragma unroll
        for (int d = 0; d < DHEAD; d++) acc[d] *= corr;

#pragma unroll
        for (int j = 0; j < TK; j++) {
            float p = __expf(sc[j] - mval);
            lsum += p;
#pragma unroll
            for (int d = 0; d < DHEAD; d++)
                acc[d] = fmaf(p, vs[j][d], acc[d]);
        }
    }

    float inv = 1.0f / lsum;
    float* orow = out + (size_t)tok * HID + h * DHEAD;
#pragma unroll
    for (int d = 0; d < DHEAD; d += 4) {
        float4 o;
        o.x = acc[d + 0] * inv;
        o.y = acc[d + 1] * inv;
        o.z = acc[d + 2] * inv;
        o.w = acc[d + 3] * inv;
        *(float4*)&orow[d] = o;
    }
}

// ---------------------------------------------------------------------------
// out[row] = LayerNorm(a[row] + b[row]) * g + be      (row width = 1024)
// grid = TOKENS, block = 256 (4 elements/thread via float4)
// ---------------------------------------------------------------------------
__global__ __launch_bounds__(256) void add_layernorm(
    const float* __restrict__ a, const float* __restrict__ bsrc,
    const float* __restrict__ g, const float* __restrict__ be,
    float* __restrict__ out)
{
    const int row = blockIdx.x;
    const int tid = threadIdx.x;

    float4 va = ((const float4*)(a + (size_t)row * HID))[tid];
    float4 vb = ((const float4*)(bsrc + (size_t)row * HID))[tid];
    float v[4] = {va.x + vb.x, va.y + vb.y, va.z + vb.z, va.w + vb.w};

    float s = v[0] + v[1] + v[2] + v[3];
    float ss = v[0] * v[0] + v[1] * v[1] + v[2] * v[2] + v[3] * v[3];

    __shared__ float r1[256];
    __shared__ float r2[256];
    r1[tid] = s;
    r2[tid] = ss;
    __syncthreads();
#pragma unroll
    for (int o = 128; o > 0; o >>= 1) {
        if (tid < o) { r1[tid] += r1[tid + o]; r2[tid] += r2[tid + o]; }
        __syncthreads();
    }
    float mu = r1[0] * (1.0f / HID);
    float var = r2[0] * (1.0f / HID) - mu * mu;
    float inv = rsqrtf(var + 1e-5f);

    float4 vg = ((const float4*)g)[tid];
    float4 vbe = ((const float4*)be)[tid];
    float4 o4;
    o4.x = (v[0] - mu) * inv * vg.x + vbe.x;
    o4.y = (v[1] - mu) * inv * vg.y + vbe.y;
    o4.z = (v[2] - mu) * inv * vg.z + vbe.z;
    o4.w = (v[3] - mu) * inv * vg.w + vbe.w;
    ((float4*)(out + (size_t)row * HID))[tid] = o4;
}

// ---------------------------------------------------------------------------
// Launch
// ---------------------------------------------------------------------------
extern "C" void kernel_launch(void* const* d_in, const int* in_sizes, int n_in,
                              void* d_out, int out_size)
{
    const float* x     = (const float*)d_in[0];
    const float* Wqkv  = (const float*)d_in[1];
    const float* bqkv  = (const float*)d_in[2];
    const float* Wproj = (const float*)d_in[3];
    const float* bproj = (const float*)d_in[4];
    const float* W1    = (const float*)d_in[5];
    const float* b1    = (const float*)d_in[6];
    const float* W2    = (const float*)d_in[7];
    const float* b2    = (const float*)d_in[8];
    const float* g1    = (const float*)d_in[9];
    const float* be1   = (const float*)d_in[10];
    const float* g2    = (const float*)d_in[11];
    const float* be2   = (const float*)d_in[12];
    float* out = (float*)d_out;

    float *qkv, *attn, *h, *ff, *tmp;
    cudaGetSymbolAddress((void**)&qkv,  g_qkv);
    cudaGetSymbolAddress((void**)&attn, g_attn);
    cudaGetSymbolAddress((void**)&h,    g_h);
    cudaGetSymbolAddress((void**)&ff,   g_ff);
    cudaGetSymbolAddress((void**)&tmp,  g_tmp);

    // 1. qkv = x @ Wqkv + bqkv        [8192,1024]x[1024,3072]
    gemm_bias_act<<<dim3(3 * HID / BN, TOKENS / BM), 256>>>(
        x, Wqkv, bqkv, qkv, TOKENS, 3 * HID, HID, 0);

    // 2. flash attention -> attn [8192,1024]
    flash_attn<<<dim3(SEQ / 128, BATCH * NHEADS), 128>>>(qkv, attn);

    // 3. tmp = attn @ Wproj + bproj
    gemm_bias_act<<<dim3(HID / BN, TOKENS / BM), 256>>>(
        attn, Wproj, bproj, tmp, TOKENS, HID, HID, 0);

    // 4. h = LN(x + tmp)
    add_layernorm<<<TOKENS, 256>>>(x, tmp, g1, be1, h);

    // 5. ff = gelu(h @ W1 + b1)       [8192,1024]x[1024,4096]
    gemm_bias_act<<<dim3(EXP / BN, TOKENS / BM), 256>>>(
        h, W1, b1, ff, TOKENS, EXP, HID, 1);

    // 6. tmp = ff @ W2 + b2           [8192,4096]x[4096,1024]
    gemm_bias_act<<<dim3(HID / BN, TOKENS / BM), 256>>>(
        ff, W2, b2, tmp, TOKENS, HID, EXP, 0);

    // 7. out = LN(h + tmp)
    add_layernorm<<<TOKENS, 256>>>(h, tmp, g2, be2, out);
}